// round 2
// baseline (speedup 1.0000x reference)
#include <cuda_runtime.h>
#include <math.h>

#define N_NODES 200000
#define HDIM 8
#define FIN 64
#define E_MAX 3000000

// ---------------- scratch (static device globals; no allocation) -------------
__device__ float g_h[3 * N_NODES * HDIM];      // h_ind, h_org, h_ext
__device__ float g_as[4 * N_NODES];            // per-edge-type src alpha
__device__ float g_ad[4 * N_NODES];            // per-edge-type dst alpha
__device__ float g_e[E_MAX];                   // per-edge exp(alpha), reused per type
__device__ float g_den[N_NODES];               // softmax denominator, reused per type
__device__ float g_out[4 * N_NODES * HDIM];    // 4 GAT outputs (pre-relu sums)
__device__ float g_score[4];                   // semantic score accumulators
__device__ float g_attw[4];                    // semantic softmax weights

// ---------------- node projection + attention alpha dots ---------------------
// h[n,:] = x[n,:] @ W + b ; then up to 3 dot products h[n,:]·att_k -> alpha arrays
__global__ void proj_kernel(const float* __restrict__ x,
                            const float* __restrict__ W,
                            const float* __restrict__ b,
                            float* __restrict__ h,
                            const float* __restrict__ a0, float* __restrict__ d0,
                            const float* __restrict__ a1, float* __restrict__ d1,
                            const float* __restrict__ a2, float* __restrict__ d2)
{
    __shared__ float sW[FIN * HDIM];
    __shared__ float sx[32][FIN + 1];
    int tid = threadIdx.x;                 // 256 threads
    for (int i = tid; i < FIN * HDIM; i += 256) sW[i] = W[i];
    int base = blockIdx.x * 32;
    for (int i = tid; i < 32 * FIN; i += 256) {
        int n = i >> 6, k = i & 63;
        int gn = base + n;
        sx[n][k] = (gn < N_NODES) ? x[(size_t)gn * FIN + k] : 0.f;
    }
    __syncthreads();

    int ln = tid >> 3;       // 0..31 local node
    int j  = tid & 7;        // output channel
    int gn = base + ln;
    float acc = __ldg(&b[j]);
#pragma unroll
    for (int k = 0; k < FIN; k++) acc += sx[ln][k] * sW[k * HDIM + j];
    if (gn < N_NODES) h[(size_t)gn * HDIM + j] = acc;

    // dot products via 8-lane xor reduction
    float v = acc * __ldg(&a0[j]);
    v += __shfl_xor_sync(0xffffffffu, v, 1);
    v += __shfl_xor_sync(0xffffffffu, v, 2);
    v += __shfl_xor_sync(0xffffffffu, v, 4);
    if (j == 0 && gn < N_NODES) d0[gn] = v;

    v = acc * __ldg(&a1[j]);
    v += __shfl_xor_sync(0xffffffffu, v, 1);
    v += __shfl_xor_sync(0xffffffffu, v, 2);
    v += __shfl_xor_sync(0xffffffffu, v, 4);
    if (j == 0 && gn < N_NODES) d1[gn] = v;

    if (a2 != nullptr) {
        v = acc * __ldg(&a2[j]);
        v += __shfl_xor_sync(0xffffffffu, v, 1);
        v += __shfl_xor_sync(0xffffffffu, v, 2);
        v += __shfl_xor_sync(0xffffffffu, v, 4);
        if (j == 0 && gn < N_NODES) d2[gn] = v;
    }
}

// ---------------- edge pass A: e = exp(leakyrelu(as[r]+ad[c])) ; den[c] += e --
__global__ void edge_a_kernel(const int* __restrict__ ei,
                              const float* __restrict__ as,
                              const float* __restrict__ ad,
                              float* __restrict__ e,
                              float* __restrict__ den, int E)
{
    int i = blockIdx.x * blockDim.x + threadIdx.x;
    if (i >= E) return;
    int r = ei[i];
    int c = ei[E + i];
    float a = __ldg(&as[r]) + __ldg(&ad[c]);
    a = (a > 0.f) ? a : 0.2f * a;
    float ex = __expf(a);
    e[i] = ex;
    atomicAdd(&den[c], ex);
}

// ---------------- invert denominators (once per node, not per edge) ----------
__global__ void inv_kernel(float* __restrict__ den)
{
    int i = blockIdx.x * blockDim.x + threadIdx.x;
    if (i < N_NODES) den[i] = 1.f / (den[i] + 1e-16f);
}

// ---------------- edge pass B: out[c,:] += h[r,:] * (e[i] * invden[c]) -------
__global__ void edge_b_kernel(const int* __restrict__ ei,
                              const float* __restrict__ e,
                              const float* __restrict__ invden,
                              const float* __restrict__ h,
                              float* __restrict__ out, int E)
{
    int i = blockIdx.x * blockDim.x + threadIdx.x;
    if (i >= E) return;
    int r = ei[i];
    int c = ei[E + i];
    float w = e[i] * __ldg(&invden[c]);
    const float4* hp = reinterpret_cast<const float4*>(h + (size_t)r * HDIM);
    float4 h0 = __ldg(hp);
    float4 h1 = __ldg(hp + 1);
    float4 m0 = make_float4(h0.x * w, h0.y * w, h0.z * w, h0.w * w);
    float4 m1 = make_float4(h1.x * w, h1.y * w, h1.z * w, h1.w * w);
    float4* op = reinterpret_cast<float4*>(out + (size_t)c * HDIM);
    atomicAdd(op, m0);       // vector red (sm_90+)
    atomicAdd(op + 1, m1);
}

// ---------------- semantic score: sum_n tanh(relu(o)@kW + kb)·q --------------
__global__ void score_kernel(const float* __restrict__ o,
                             const float* __restrict__ kW,
                             const float* __restrict__ kb,
                             const float* __restrict__ q,
                             float* __restrict__ score)
{
    int n = blockIdx.x * blockDim.x + threadIdx.x;
    float s = 0.f;
    if (n < N_NODES) {
        const float4* op = reinterpret_cast<const float4*>(o + (size_t)n * HDIM);
        float4 o0 = __ldg(op), o1 = __ldg(op + 1);
        float orl[HDIM];
        orl[0] = fmaxf(o0.x, 0.f); orl[1] = fmaxf(o0.y, 0.f);
        orl[2] = fmaxf(o0.z, 0.f); orl[3] = fmaxf(o0.w, 0.f);
        orl[4] = fmaxf(o1.x, 0.f); orl[5] = fmaxf(o1.y, 0.f);
        orl[6] = fmaxf(o1.z, 0.f); orl[7] = fmaxf(o1.w, 0.f);
#pragma unroll
        for (int j = 0; j < HDIM; j++) {
            float acc = __ldg(&kb[j]);
#pragma unroll
            for (int k = 0; k < HDIM; k++) acc += orl[k] * __ldg(&kW[k * HDIM + j]);
            s += __ldg(&q[j]) * tanhf(acc);
        }
    }
    // block reduction
#pragma unroll
    for (int off = 16; off; off >>= 1) s += __shfl_xor_sync(0xffffffffu, s, off);
    __shared__ float ws[8];
    int lane = threadIdx.x & 31, wid = threadIdx.x >> 5;
    if (lane == 0) ws[wid] = s;
    __syncthreads();
    if (wid == 0) {
        s = (lane < 8) ? ws[lane] : 0.f;
#pragma unroll
        for (int off = 4; off; off >>= 1) s += __shfl_xor_sync(0xffffffffu, s, off);
        if (lane == 0) atomicAdd(score, s);
    }
}

// ---------------- semantic softmax over the 2 metapaths per group ------------
__global__ void attn_kernel(const float* __restrict__ score, float* __restrict__ w)
{
#pragma unroll
    for (int g = 0; g < 2; g++) {
        float s0 = score[2 * g]     * (1.f / (float)N_NODES);
        float s1 = score[2 * g + 1] * (1.f / (float)N_NODES);
        float m  = fmaxf(s0, s1);
        float e0 = expf(s0 - m), e1 = expf(s1 - m);
        float inv = 1.f / (e0 + e1);
        w[2 * g] = e0 * inv;
        w[2 * g + 1] = e1 * inv;
    }
}

// ---------------- final: z = w0*relu(o0)+w1*relu(o1); pred = sigmoid(z·W+b) --
__global__ void final_kernel(const float* __restrict__ o0,
                             const float* __restrict__ o1,
                             const float* __restrict__ attw,   // pointer to this group's 2 weights
                             const float* __restrict__ linW,
                             const float* __restrict__ linb,
                             float* __restrict__ pred)
{
    int n = blockIdx.x * blockDim.x + threadIdx.x;
    if (n >= N_NODES) return;
    float w0 = attw[0], w1 = attw[1];
    float s = __ldg(&linb[0]);
#pragma unroll
    for (int j = 0; j < HDIM; j++) {
        float z = w0 * fmaxf(o0[(size_t)n * HDIM + j], 0.f)
                + w1 * fmaxf(o1[(size_t)n * HDIM + j], 0.f);
        s += z * __ldg(&linW[j]);
    }
    pred[n] = 1.f / (1.f + expf(-s));
}

// -----------------------------------------------------------------------------
extern "C" void kernel_launch(void* const* d_in, const int* in_sizes, int n_in,
                              void* d_out, int out_size)
{
    // input order per metadata:
    // 0 x_ind, 1 x_org, 2 x_ext,
    // 3 ei_ind_org, 4 ei_org_ind, 5 ei_ext_ind, 6 ei_ext_org,
    // 7 W_ind, 8 b_ind, 9 W_org, 10 b_org, 11 W_ext, 12 b_ext,
    // 13 as_ind_org, 14 ad_ind_org, 15 as_org_ind, 16 ad_org_ind,
    // 17 as_ext_ind, 18 ad_ext_ind, 19 as_ext_org, 20 ad_ext_org,
    // 21 k_W, 22 k_b, 23 q, 24 lin_ind_W, 25 lin_ind_b, 26 lin_org_W, 27 lin_org_b
    const float* x[3] = { (const float*)d_in[0], (const float*)d_in[1], (const float*)d_in[2] };
    const int*   ei_ind_org = (const int*)d_in[3];
    const int*   ei_org_ind = (const int*)d_in[4];
    const int*   ei_ext_ind = (const int*)d_in[5];
    const int*   ei_ext_org = (const int*)d_in[6];
    const int E = in_sizes[3] / 2;

    float *p_h, *p_as, *p_ad, *p_e, *p_den, *p_out, *p_score, *p_attw;
    cudaGetSymbolAddress((void**)&p_h, g_h);
    cudaGetSymbolAddress((void**)&p_as, g_as);
    cudaGetSymbolAddress((void**)&p_ad, g_ad);
    cudaGetSymbolAddress((void**)&p_e, g_e);
    cudaGetSymbolAddress((void**)&p_den, g_den);
    cudaGetSymbolAddress((void**)&p_out, g_out);
    cudaGetSymbolAddress((void**)&p_score, g_score);
    cudaGetSymbolAddress((void**)&p_attw, g_attw);

    float* h_ind = p_h;
    float* h_org = p_h + (size_t)N_NODES * HDIM;
    float* h_ext = p_h + 2 * (size_t)N_NODES * HDIM;

    cudaMemsetAsync(p_out, 0, 4 * (size_t)N_NODES * HDIM * sizeof(float), 0);
    cudaMemsetAsync(p_score, 0, 4 * sizeof(float), 0);

    const int PROJ_GRID = (N_NODES + 31) / 32;
    // node type ind: dst alphas for org->ind (t0), ext->ind (t1); src alpha for ind->org (t2)
    proj_kernel<<<PROJ_GRID, 256>>>(x[0], (const float*)d_in[7], (const float*)d_in[8], h_ind,
        (const float*)d_in[16], p_ad + 0 * N_NODES,
        (const float*)d_in[18], p_ad + 1 * N_NODES,
        (const float*)d_in[13], p_as + 2 * N_NODES);
    // node type org: src alpha for org->ind (t0); dst alphas for ind->org (t2), ext->org (t3)
    proj_kernel<<<PROJ_GRID, 256>>>(x[1], (const float*)d_in[9], (const float*)d_in[10], h_org,
        (const float*)d_in[15], p_as + 0 * N_NODES,
        (const float*)d_in[14], p_ad + 2 * N_NODES,
        (const float*)d_in[20], p_ad + 3 * N_NODES);
    // node type ext: src alphas for ext->ind (t1), ext->org (t3)
    proj_kernel<<<PROJ_GRID, 256>>>(x[2], (const float*)d_in[11], (const float*)d_in[12], h_ext,
        (const float*)d_in[17], p_as + 1 * N_NODES,
        (const float*)d_in[19], p_as + 3 * N_NODES,
        nullptr, nullptr);

    // edge type table: t0=org->ind, t1=ext->ind, t2=ind->org, t3=ext->org
    const int*  ei_t[4]  = { ei_org_ind, ei_ext_ind, ei_ind_org, ei_ext_org };
    const float* hs_t[4] = { h_org, h_ext, h_ind, h_ext };

    const int EG = (E + 255) / 256;
    const int NG = (N_NODES + 255) / 256;
    for (int t = 0; t < 4; t++) {
        cudaMemsetAsync(p_den, 0, N_NODES * sizeof(float), 0);
        edge_a_kernel<<<EG, 256>>>(ei_t[t], p_as + (size_t)t * N_NODES,
                                   p_ad + (size_t)t * N_NODES, p_e, p_den, E);
        inv_kernel<<<NG, 256>>>(p_den);
        edge_b_kernel<<<EG, 256>>>(ei_t[t], p_e, p_den, hs_t[t],
                                   p_out + (size_t)t * N_NODES * HDIM, E);
    }

    // semantic attention
    for (int g = 0; g < 4; g++) {
        score_kernel<<<NG, 256>>>(p_out + (size_t)g * N_NODES * HDIM,
                                  (const float*)d_in[21], (const float*)d_in[22],
                                  (const float*)d_in[23], p_score + g);
    }
    attn_kernel<<<1, 1>>>(p_score, p_attw);

    float* pred = (float*)d_out;
    final_kernel<<<NG, 256>>>(p_out + 0 * (size_t)N_NODES * HDIM,
                              p_out + 1 * (size_t)N_NODES * HDIM,
                              p_attw + 0, (const float*)d_in[24], (const float*)d_in[25],
                              pred);
    final_kernel<<<NG, 256>>>(p_out + 2 * (size_t)N_NODES * HDIM,
                              p_out + 3 * (size_t)N_NODES * HDIM,
                              p_attw + 2, (const float*)d_in[26], (const float*)d_in[27],
                              pred + N_NODES);
}

// round 3
// speedup vs baseline: 1.1036x; 1.1036x over previous
#include <cuda_runtime.h>
#include <math.h>

#define N_NODES 200000
#define HDIM 8
#define FIN 64

// ---------------- scratch (static device globals; no allocation) -------------
__device__ float g_h[3 * N_NODES * HDIM];      // h_ind, h_org, h_ext
__device__ float g_as[4 * N_NODES];            // per-edge-type src alpha
__device__ float g_ad[4 * N_NODES];            // per-edge-type dst alpha
__device__ float g_den[4 * N_NODES];           // per-type softmax denominators
__device__ float g_out[4 * N_NODES * HDIM];    // 4 GAT outputs (UNNORMALIZED sums)
__device__ float g_score[4];                   // semantic score accumulators
__device__ float g_attw[4];                    // semantic softmax weights

// ---------------- node projection + attention alpha dots ---------------------
__global__ void proj_kernel(const float* __restrict__ x,
                            const float* __restrict__ W,
                            const float* __restrict__ b,
                            float* __restrict__ h,
                            const float* __restrict__ a0, float* __restrict__ d0,
                            const float* __restrict__ a1, float* __restrict__ d1,
                            const float* __restrict__ a2, float* __restrict__ d2)
{
    __shared__ float sW[FIN * HDIM];
    __shared__ float sx[32][FIN + 1];
    int tid = threadIdx.x;                 // 256 threads
    for (int i = tid; i < FIN * HDIM; i += 256) sW[i] = W[i];
    int base = blockIdx.x * 32;
    for (int i = tid; i < 32 * FIN; i += 256) {
        int n = i >> 6, k = i & 63;
        int gn = base + n;
        sx[n][k] = (gn < N_NODES) ? x[(size_t)gn * FIN + k] : 0.f;
    }
    __syncthreads();

    int ln = tid >> 3;       // 0..31 local node
    int j  = tid & 7;        // output channel
    int gn = base + ln;
    float acc = __ldg(&b[j]);
#pragma unroll
    for (int k = 0; k < FIN; k++) acc += sx[ln][k] * sW[k * HDIM + j];
    if (gn < N_NODES) h[(size_t)gn * HDIM + j] = acc;

    float v = acc * __ldg(&a0[j]);
    v += __shfl_xor_sync(0xffffffffu, v, 1);
    v += __shfl_xor_sync(0xffffffffu, v, 2);
    v += __shfl_xor_sync(0xffffffffu, v, 4);
    if (j == 0 && gn < N_NODES) d0[gn] = v;

    v = acc * __ldg(&a1[j]);
    v += __shfl_xor_sync(0xffffffffu, v, 1);
    v += __shfl_xor_sync(0xffffffffu, v, 2);
    v += __shfl_xor_sync(0xffffffffu, v, 4);
    if (j == 0 && gn < N_NODES) d1[gn] = v;

    if (a2 != nullptr) {
        v = acc * __ldg(&a2[j]);
        v += __shfl_xor_sync(0xffffffffu, v, 1);
        v += __shfl_xor_sync(0xffffffffu, v, 2);
        v += __shfl_xor_sync(0xffffffffu, v, 4);
        if (j == 0 && gn < N_NODES) d2[gn] = v;
    }
}

// ---------------- single fused edge pass --------------------------------------
// ex = exp(leakyrelu(as[r]+ad[c])); den[c] += ex; out[c,:] += ex * h[r,:]
// 4 edges per thread via int4 index loads for MLP.
__global__ void edge_fused_kernel(const int* __restrict__ ei,
                                  const float* __restrict__ as,
                                  const float* __restrict__ ad,
                                  const float* __restrict__ h,
                                  float* __restrict__ den,
                                  float* __restrict__ out, int E)
{
    int i0 = (blockIdx.x * blockDim.x + threadIdx.x) * 4;
    if (i0 >= E) return;
    int4 rr = *reinterpret_cast<const int4*>(ei + i0);
    int4 cc = *reinterpret_cast<const int4*>(ei + E + i0);
    int r[4] = { rr.x, rr.y, rr.z, rr.w };
    int c[4] = { cc.x, cc.y, cc.z, cc.w };

    float a_s[4], a_d[4];
#pragma unroll
    for (int k = 0; k < 4; k++) a_s[k] = __ldg(&as[r[k]]);
#pragma unroll
    for (int k = 0; k < 4; k++) a_d[k] = __ldg(&ad[c[k]]);

    float4 h0[4], h1[4];
#pragma unroll
    for (int k = 0; k < 4; k++) {
        const float4* hp = reinterpret_cast<const float4*>(h + (size_t)r[k] * HDIM);
        h0[k] = __ldg(hp);
        h1[k] = __ldg(hp + 1);
    }

#pragma unroll
    for (int k = 0; k < 4; k++) {
        float a = a_s[k] + a_d[k];
        a = (a > 0.f) ? a : 0.2f * a;
        float ex = __expf(a);
        atomicAdd(&den[c[k]], ex);
        float4 m0 = make_float4(h0[k].x * ex, h0[k].y * ex, h0[k].z * ex, h0[k].w * ex);
        float4 m1 = make_float4(h1[k].x * ex, h1[k].y * ex, h1[k].z * ex, h1[k].w * ex);
        float4* op = reinterpret_cast<float4*>(out + (size_t)c[k] * HDIM);
        atomicAdd(op, m0);        // vector red (sm_90+)
        atomicAdd(op + 1, m1);
    }
}

// ---------------- invert all 4 denominator arrays at once --------------------
__global__ void inv_kernel(float* __restrict__ den)
{
    int i = blockIdx.x * blockDim.x + threadIdx.x;
    if (i < 4 * N_NODES) den[i] = 1.f / (den[i] + 1e-16f);
}

// ---------------- semantic score: sum_n tanh(relu(o*inv)@kW + kb)·q ----------
__global__ void score_kernel(const float* __restrict__ o,
                             const float* __restrict__ invden,
                             const float* __restrict__ kW,
                             const float* __restrict__ kb,
                             const float* __restrict__ q,
                             float* __restrict__ score)
{
    int n = blockIdx.x * blockDim.x + threadIdx.x;
    float s = 0.f;
    if (n < N_NODES) {
        float inv = __ldg(&invden[n]);
        const float4* op = reinterpret_cast<const float4*>(o + (size_t)n * HDIM);
        float4 o0 = __ldg(op), o1 = __ldg(op + 1);
        float orl[HDIM];
        orl[0] = fmaxf(o0.x * inv, 0.f); orl[1] = fmaxf(o0.y * inv, 0.f);
        orl[2] = fmaxf(o0.z * inv, 0.f); orl[3] = fmaxf(o0.w * inv, 0.f);
        orl[4] = fmaxf(o1.x * inv, 0.f); orl[5] = fmaxf(o1.y * inv, 0.f);
        orl[6] = fmaxf(o1.z * inv, 0.f); orl[7] = fmaxf(o1.w * inv, 0.f);
#pragma unroll
        for (int j = 0; j < HDIM; j++) {
            float acc = __ldg(&kb[j]);
#pragma unroll
            for (int k = 0; k < HDIM; k++) acc += orl[k] * __ldg(&kW[k * HDIM + j]);
            s += __ldg(&q[j]) * tanhf(acc);
        }
    }
#pragma unroll
    for (int off = 16; off; off >>= 1) s += __shfl_xor_sync(0xffffffffu, s, off);
    __shared__ float ws[8];
    int lane = threadIdx.x & 31, wid = threadIdx.x >> 5;
    if (lane == 0) ws[wid] = s;
    __syncthreads();
    if (wid == 0) {
        s = (lane < 8) ? ws[lane] : 0.f;
#pragma unroll
        for (int off = 4; off; off >>= 1) s += __shfl_xor_sync(0xffffffffu, s, off);
        if (lane == 0) atomicAdd(score, s);
    }
}

// ---------------- semantic softmax over the 2 metapaths per group ------------
__global__ void attn_kernel(const float* __restrict__ score, float* __restrict__ w)
{
#pragma unroll
    for (int g = 0; g < 2; g++) {
        float s0 = score[2 * g]     * (1.f / (float)N_NODES);
        float s1 = score[2 * g + 1] * (1.f / (float)N_NODES);
        float m  = fmaxf(s0, s1);
        float e0 = expf(s0 - m), e1 = expf(s1 - m);
        float inv = 1.f / (e0 + e1);
        w[2 * g] = e0 * inv;
        w[2 * g + 1] = e1 * inv;
    }
}

// ---------------- final: z = w0*relu(o0*i0)+w1*relu(o1*i1); sigmoid(z·W+b) ---
__global__ void final_kernel(const float* __restrict__ o0,
                             const float* __restrict__ inv0,
                             const float* __restrict__ o1,
                             const float* __restrict__ inv1,
                             const float* __restrict__ attw,
                             const float* __restrict__ linW,
                             const float* __restrict__ linb,
                             float* __restrict__ pred)
{
    int n = blockIdx.x * blockDim.x + threadIdx.x;
    if (n >= N_NODES) return;
    float w0 = attw[0], w1 = attw[1];
    float i0 = __ldg(&inv0[n]), i1 = __ldg(&inv1[n]);
    float s = __ldg(&linb[0]);
#pragma unroll
    for (int j = 0; j < HDIM; j++) {
        float z = w0 * fmaxf(o0[(size_t)n * HDIM + j] * i0, 0.f)
                + w1 * fmaxf(o1[(size_t)n * HDIM + j] * i1, 0.f);
        s += z * __ldg(&linW[j]);
    }
    pred[n] = 1.f / (1.f + expf(-s));
}

// -----------------------------------------------------------------------------
extern "C" void kernel_launch(void* const* d_in, const int* in_sizes, int n_in,
                              void* d_out, int out_size)
{
    const float* x[3] = { (const float*)d_in[0], (const float*)d_in[1], (const float*)d_in[2] };
    const int*   ei_ind_org = (const int*)d_in[3];
    const int*   ei_org_ind = (const int*)d_in[4];
    const int*   ei_ext_ind = (const int*)d_in[5];
    const int*   ei_ext_org = (const int*)d_in[6];
    const int E = in_sizes[3] / 2;

    float *p_h, *p_as, *p_ad, *p_den, *p_out, *p_score, *p_attw;
    cudaGetSymbolAddress((void**)&p_h, g_h);
    cudaGetSymbolAddress((void**)&p_as, g_as);
    cudaGetSymbolAddress((void**)&p_ad, g_ad);
    cudaGetSymbolAddress((void**)&p_den, g_den);
    cudaGetSymbolAddress((void**)&p_out, g_out);
    cudaGetSymbolAddress((void**)&p_score, g_score);
    cudaGetSymbolAddress((void**)&p_attw, g_attw);

    float* h_ind = p_h;
    float* h_org = p_h + (size_t)N_NODES * HDIM;
    float* h_ext = p_h + 2 * (size_t)N_NODES * HDIM;

    cudaMemsetAsync(p_out, 0, 4 * (size_t)N_NODES * HDIM * sizeof(float), 0);
    cudaMemsetAsync(p_den, 0, 4 * (size_t)N_NODES * sizeof(float), 0);
    cudaMemsetAsync(p_score, 0, 4 * sizeof(float), 0);

    const int PROJ_GRID = (N_NODES + 31) / 32;
    // ind: dst alphas for org->ind (t0), ext->ind (t1); src alpha for ind->org (t2)
    proj_kernel<<<PROJ_GRID, 256>>>(x[0], (const float*)d_in[7], (const float*)d_in[8], h_ind,
        (const float*)d_in[16], p_ad + 0 * N_NODES,
        (const float*)d_in[18], p_ad + 1 * N_NODES,
        (const float*)d_in[13], p_as + 2 * N_NODES);
    // org: src alpha for org->ind (t0); dst alphas for ind->org (t2), ext->org (t3)
    proj_kernel<<<PROJ_GRID, 256>>>(x[1], (const float*)d_in[9], (const float*)d_in[10], h_org,
        (const float*)d_in[15], p_as + 0 * N_NODES,
        (const float*)d_in[14], p_ad + 2 * N_NODES,
        (const float*)d_in[20], p_ad + 3 * N_NODES);
    // ext: src alphas for ext->ind (t1), ext->org (t3)
    proj_kernel<<<PROJ_GRID, 256>>>(x[2], (const float*)d_in[11], (const float*)d_in[12], h_ext,
        (const float*)d_in[17], p_as + 1 * N_NODES,
        (const float*)d_in[19], p_as + 3 * N_NODES,
        nullptr, nullptr);

    // edge type table: t0=org->ind, t1=ext->ind, t2=ind->org, t3=ext->org
    const int*  ei_t[4]  = { ei_org_ind, ei_ext_ind, ei_ind_org, ei_ext_org };
    const float* hs_t[4] = { h_org, h_ext, h_ind, h_ext };

    const int EG4 = (E / 4 + 255) / 256;
    for (int t = 0; t < 4; t++) {
        edge_fused_kernel<<<EG4, 256>>>(ei_t[t],
                                        p_as + (size_t)t * N_NODES,
                                        p_ad + (size_t)t * N_NODES,
                                        hs_t[t],
                                        p_den + (size_t)t * N_NODES,
                                        p_out + (size_t)t * N_NODES * HDIM, E);
    }

    const int NG = (N_NODES + 255) / 256;
    inv_kernel<<<(4 * N_NODES + 255) / 256, 256>>>(p_den);

    for (int g = 0; g < 4; g++) {
        score_kernel<<<NG, 256>>>(p_out + (size_t)g * N_NODES * HDIM,
                                  p_den + (size_t)g * N_NODES,
                                  (const float*)d_in[21], (const float*)d_in[22],
                                  (const float*)d_in[23], p_score + g);
    }
    attn_kernel<<<1, 1>>>(p_score, p_attw);

    float* pred = (float*)d_out;
    final_kernel<<<NG, 256>>>(p_out + 0 * (size_t)N_NODES * HDIM, p_den + 0 * N_NODES,
                              p_out + 1 * (size_t)N_NODES * HDIM, p_den + 1 * N_NODES,
                              p_attw + 0, (const float*)d_in[24], (const float*)d_in[25],
                              pred);
    final_kernel<<<NG, 256>>>(p_out + 2 * (size_t)N_NODES * HDIM, p_den + 2 * N_NODES,
                              p_out + 3 * (size_t)N_NODES * HDIM, p_den + 3 * N_NODES,
                              p_attw + 2, (const float*)d_in[26], (const float*)d_in[27],
                              pred + N_NODES);
}

// round 4
// speedup vs baseline: 1.3019x; 1.1797x over previous
#include <cuda_runtime.h>
#include <cuda_fp16.h>
#include <math.h>

#define N_NODES 200000
#define HDIM 8
#define FIN 64
#define ROWB 32   // packed src row: 16B fp16 h + 4B fp32 as + 12B pad

// ---------------- scratch (static device globals; no allocation) -------------
__device__ char  g_pack[4][(size_t)N_NODES * ROWB]; // per edge type: packed src rows
__device__ float g_ad[4 * N_NODES];                 // per edge type: dst alpha
__device__ float g_den[4 * N_NODES];                // per-type softmax denominators
__device__ float g_out[4 * N_NODES * HDIM];         // 4 GAT outputs (UNNORMALIZED)
__device__ float g_score[4];
__device__ float g_attw[4];

// ---------------- fused projection (all 3 node types, grid.y) ----------------
struct ProjP {
    const float *x, *W, *b;
    const float *a_p0; char *pack0;    // packed src row output 0 (nullable)
    const float *a_p1; char *pack1;    // packed src row output 1 (nullable)
    const float *a_d0; float *d0;      // dst alpha output 0 (nullable)
    const float *a_d1; float *d1;      // dst alpha output 1 (nullable)
};
struct ProjAll { ProjP t[3]; };

__global__ void proj_kernel(ProjAll A)
{
    const ProjP P = A.t[blockIdx.y];
    __shared__ float sW[FIN * HDIM];
    __shared__ float sx[32][FIN + 1];
    int tid = threadIdx.x;                 // 256 threads, 32 nodes/block
    for (int i = tid; i < FIN * HDIM; i += 256) sW[i] = P.W[i];
    int base = blockIdx.x * 32;            // N_NODES % 32 == 0
    for (int i = tid; i < 32 * FIN; i += 256) {
        int n = i >> 6, k = i & 63;
        sx[n][k] = P.x[(size_t)(base + n) * FIN + k];
    }
    __syncthreads();

    int ln = tid >> 3;       // local node
    int j  = tid & 7;        // channel
    int gn = base + ln;
    float acc = __ldg(&P.b[j]);
#pragma unroll
    for (int k = 0; k < FIN; k++) acc += sx[ln][k] * sW[k * HDIM + j];

    if (P.pack0) {
        char* row = P.pack0 + (size_t)gn * ROWB;
        *reinterpret_cast<__half*>(row + 2 * j) = __float2half(acc);
        float v = acc * __ldg(&P.a_p0[j]);
        v += __shfl_xor_sync(0xffffffffu, v, 1);
        v += __shfl_xor_sync(0xffffffffu, v, 2);
        v += __shfl_xor_sync(0xffffffffu, v, 4);
        if (j == 0) *reinterpret_cast<float*>(row + 16) = v;
    }
    if (P.pack1) {
        char* row = P.pack1 + (size_t)gn * ROWB;
        *reinterpret_cast<__half*>(row + 2 * j) = __float2half(acc);
        float v = acc * __ldg(&P.a_p1[j]);
        v += __shfl_xor_sync(0xffffffffu, v, 1);
        v += __shfl_xor_sync(0xffffffffu, v, 2);
        v += __shfl_xor_sync(0xffffffffu, v, 4);
        if (j == 0) *reinterpret_cast<float*>(row + 16) = v;
    }
    if (P.d0) {
        float v = acc * __ldg(&P.a_d0[j]);
        v += __shfl_xor_sync(0xffffffffu, v, 1);
        v += __shfl_xor_sync(0xffffffffu, v, 2);
        v += __shfl_xor_sync(0xffffffffu, v, 4);
        if (j == 0) P.d0[gn] = v;
    }
    if (P.d1) {
        float v = acc * __ldg(&P.a_d1[j]);
        v += __shfl_xor_sync(0xffffffffu, v, 1);
        v += __shfl_xor_sync(0xffffffffu, v, 2);
        v += __shfl_xor_sync(0xffffffffu, v, 4);
        if (j == 0) P.d1[gn] = v;
    }
}

// ---------------- fused edge pass (all 4 edge types, grid.y) -----------------
struct EdgeAll {
    const int*  ei[4];
    const char* pack[4];
    const float* ad[4];
    float* den[4];
    float* out[4];
    int E[4];
};

__device__ __forceinline__ void edge_one(int r, int c,
                                         const char* __restrict__ pack,
                                         const float* __restrict__ ad,
                                         float* __restrict__ den,
                                         float* __restrict__ out)
{
    const uint4* rowp = reinterpret_cast<const uint4*>(pack + (size_t)r * ROWB);
    uint4 hv = __ldg(rowp);                                     // 8 fp16 h
    float asv = __ldg(reinterpret_cast<const float*>(rowp) + 4); // same 32B sector
    float a = asv + __ldg(&ad[c]);
    a = (a > 0.f) ? a : 0.2f * a;
    float ex = __expf(a);

    const __half2* hp = reinterpret_cast<const __half2*>(&hv);
    float2 f0 = __half22float2(hp[0]);
    float2 f1 = __half22float2(hp[1]);
    float2 f2 = __half22float2(hp[2]);
    float2 f3 = __half22float2(hp[3]);

    float4* op = reinterpret_cast<float4*>(out + (size_t)c * HDIM);
    atomicAdd(op,     make_float4(f0.x * ex, f0.y * ex, f1.x * ex, f1.y * ex));
    atomicAdd(op + 1, make_float4(f2.x * ex, f2.y * ex, f3.x * ex, f3.y * ex));
    atomicAdd(&den[c], ex);
}

__global__ void edge_kernel(EdgeAll A)
{
    int t = blockIdx.y;
    int E = A.E[t];
    const int*  ei   = A.ei[t];
    const char* pack = A.pack[t];
    const float* ad  = A.ad[t];
    float* den = A.den[t];
    float* out = A.out[t];

    int i0 = (blockIdx.x * blockDim.x + threadIdx.x) * 4;
    if (i0 + 4 <= E) {
        int4 rr = *reinterpret_cast<const int4*>(ei + i0);
        int4 cc = *reinterpret_cast<const int4*>(ei + E + i0);
        edge_one(rr.x, cc.x, pack, ad, den, out);
        edge_one(rr.y, cc.y, pack, ad, den, out);
        edge_one(rr.z, cc.z, pack, ad, den, out);
        edge_one(rr.w, cc.w, pack, ad, den, out);
    } else {
        for (int i = i0; i < E; i++)
            edge_one(ei[i], ei[E + i], pack, ad, den, out);
    }
}

// ---------------- semantic score (all 4 metapaths, grid.y); inv inline -------
__global__ void score_kernel(const float* __restrict__ out_base,
                             const float* __restrict__ den_base,
                             const float* __restrict__ kW,
                             const float* __restrict__ kb,
                             const float* __restrict__ q,
                             float* __restrict__ score)
{
    int g = blockIdx.y;
    const float* o = out_base + (size_t)g * N_NODES * HDIM;
    const float* den = den_base + (size_t)g * N_NODES;
    int n = blockIdx.x * blockDim.x + threadIdx.x;
    float s = 0.f;
    if (n < N_NODES) {
        float inv = 1.f / (__ldg(&den[n]) + 1e-16f);
        const float4* op = reinterpret_cast<const float4*>(o + (size_t)n * HDIM);
        float4 o0 = __ldg(op), o1 = __ldg(op + 1);
        float orl[HDIM];
        orl[0] = fmaxf(o0.x * inv, 0.f); orl[1] = fmaxf(o0.y * inv, 0.f);
        orl[2] = fmaxf(o0.z * inv, 0.f); orl[3] = fmaxf(o0.w * inv, 0.f);
        orl[4] = fmaxf(o1.x * inv, 0.f); orl[5] = fmaxf(o1.y * inv, 0.f);
        orl[6] = fmaxf(o1.z * inv, 0.f); orl[7] = fmaxf(o1.w * inv, 0.f);
#pragma unroll
        for (int j = 0; j < HDIM; j++) {
            float acc = __ldg(&kb[j]);
#pragma unroll
            for (int k = 0; k < HDIM; k++) acc += orl[k] * __ldg(&kW[k * HDIM + j]);
            s += __ldg(&q[j]) * tanhf(acc);
        }
    }
#pragma unroll
    for (int off = 16; off; off >>= 1) s += __shfl_xor_sync(0xffffffffu, s, off);
    __shared__ float ws[8];
    int lane = threadIdx.x & 31, wid = threadIdx.x >> 5;
    if (lane == 0) ws[wid] = s;
    __syncthreads();
    if (wid == 0) {
        s = (lane < 8) ? ws[lane] : 0.f;
#pragma unroll
        for (int off = 4; off; off >>= 1) s += __shfl_xor_sync(0xffffffffu, s, off);
        if (lane == 0) atomicAdd(&score[g], s);
    }
}

// ---------------- semantic softmax over the 2 metapaths per group ------------
__global__ void attn_kernel(const float* __restrict__ score, float* __restrict__ w)
{
#pragma unroll
    for (int g = 0; g < 2; g++) {
        float s0 = score[2 * g]     * (1.f / (float)N_NODES);
        float s1 = score[2 * g + 1] * (1.f / (float)N_NODES);
        float m  = fmaxf(s0, s1);
        float e0 = expf(s0 - m), e1 = expf(s1 - m);
        float inv = 1.f / (e0 + e1);
        w[2 * g] = e0 * inv;
        w[2 * g + 1] = e1 * inv;
    }
}

// ---------------- final heads (both groups, grid.y); inv inline --------------
struct FinP {
    const float* linW;
    const float* linb;
};
__global__ void final_kernel(const float* __restrict__ out_base,
                             const float* __restrict__ den_base,
                             const float* __restrict__ attw,
                             FinP f0p, FinP f1p,
                             float* __restrict__ pred)
{
    int g = blockIdx.y;   // 0: ind (types 0,1), 1: org (types 2,3)
    int n = blockIdx.x * blockDim.x + threadIdx.x;
    if (n >= N_NODES) return;
    const float* o0 = out_base + (size_t)(2 * g)     * N_NODES * HDIM;
    const float* o1 = out_base + (size_t)(2 * g + 1) * N_NODES * HDIM;
    float i0 = 1.f / (__ldg(&den_base[(size_t)(2 * g)     * N_NODES + n]) + 1e-16f);
    float i1 = 1.f / (__ldg(&den_base[(size_t)(2 * g + 1) * N_NODES + n]) + 1e-16f);
    float w0 = attw[2 * g], w1 = attw[2 * g + 1];
    const float* linW = g ? f1p.linW : f0p.linW;
    const float* linb = g ? f1p.linb : f0p.linb;
    float s = __ldg(&linb[0]);
#pragma unroll
    for (int j = 0; j < HDIM; j++) {
        float z = w0 * fmaxf(o0[(size_t)n * HDIM + j] * i0, 0.f)
                + w1 * fmaxf(o1[(size_t)n * HDIM + j] * i1, 0.f);
        s += z * __ldg(&linW[j]);
    }
    pred[(size_t)g * N_NODES + n] = 1.f / (1.f + expf(-s));
}

// -----------------------------------------------------------------------------
extern "C" void kernel_launch(void* const* d_in, const int* in_sizes, int n_in,
                              void* d_out, int out_size)
{
    char  *p_pack; float *p_ad, *p_den, *p_out, *p_score, *p_attw;
    cudaGetSymbolAddress((void**)&p_pack, g_pack);
    cudaGetSymbolAddress((void**)&p_ad, g_ad);
    cudaGetSymbolAddress((void**)&p_den, g_den);
    cudaGetSymbolAddress((void**)&p_out, g_out);
    cudaGetSymbolAddress((void**)&p_score, g_score);
    cudaGetSymbolAddress((void**)&p_attw, g_attw);

    char* pk[4];
    for (int t = 0; t < 4; t++) pk[t] = p_pack + (size_t)t * N_NODES * ROWB;

    cudaMemsetAsync(p_out, 0, 4 * (size_t)N_NODES * HDIM * sizeof(float), 0);
    cudaMemsetAsync(p_den, 0, 4 * (size_t)N_NODES * sizeof(float), 0);
    cudaMemsetAsync(p_score, 0, 4 * sizeof(float), 0);

    // edge types: t0=org->ind, t1=ext->ind, t2=ind->org, t3=ext->org
    ProjAll PA;
    // ind: pack t2 (src of ind->org, att_src d_in[13]); ad t0 (d_in[16]), ad t1 (d_in[18])
    PA.t[0] = { (const float*)d_in[0], (const float*)d_in[7], (const float*)d_in[8],
                (const float*)d_in[13], pk[2],  nullptr, nullptr,
                (const float*)d_in[16], p_ad + 0 * N_NODES,
                (const float*)d_in[18], p_ad + 1 * N_NODES };
    // org: pack t0 (att_src d_in[15]); ad t2 (d_in[14]), ad t3 (d_in[20])
    PA.t[1] = { (const float*)d_in[1], (const float*)d_in[9], (const float*)d_in[10],
                (const float*)d_in[15], pk[0],  nullptr, nullptr,
                (const float*)d_in[14], p_ad + 2 * N_NODES,
                (const float*)d_in[20], p_ad + 3 * N_NODES };
    // ext: pack t1 (att_src d_in[17]), pack t3 (att_src d_in[19])
    PA.t[2] = { (const float*)d_in[2], (const float*)d_in[11], (const float*)d_in[12],
                (const float*)d_in[17], pk[1],
                (const float*)d_in[19], pk[3],
                nullptr, nullptr, nullptr, nullptr };

    dim3 pg(N_NODES / 32, 3);
    proj_kernel<<<pg, 256>>>(PA);

    EdgeAll EA;
    EA.ei[0] = (const int*)d_in[4]; EA.E[0] = in_sizes[4] / 2;  // org->ind
    EA.ei[1] = (const int*)d_in[5]; EA.E[1] = in_sizes[5] / 2;  // ext->ind
    EA.ei[2] = (const int*)d_in[3]; EA.E[2] = in_sizes[3] / 2;  // ind->org
    EA.ei[3] = (const int*)d_in[6]; EA.E[3] = in_sizes[6] / 2;  // ext->org
    int Emax = 0;
    for (int t = 0; t < 4; t++) {
        EA.pack[t] = pk[t];
        EA.ad[t]   = p_ad + (size_t)t * N_NODES;
        EA.den[t]  = p_den + (size_t)t * N_NODES;
        EA.out[t]  = p_out + (size_t)t * N_NODES * HDIM;
        if (EA.E[t] > Emax) Emax = EA.E[t];
    }
    dim3 eg((Emax / 4 + 255) / 256 + 1, 4);
    edge_kernel<<<eg, 256>>>(EA);

    const int NG = (N_NODES + 255) / 256;
    dim3 sg(NG, 4);
    score_kernel<<<sg, 256>>>(p_out, p_den,
                              (const float*)d_in[21], (const float*)d_in[22],
                              (const float*)d_in[23], p_score);
    attn_kernel<<<1, 1>>>(p_score, p_attw);

    FinP f0 = { (const float*)d_in[24], (const float*)d_in[25] };
    FinP f1 = { (const float*)d_in[26], (const float*)d_in[27] };
    dim3 fg(NG, 2);
    final_kernel<<<fg, 256>>>(p_out, p_den, p_attw, f0, f1, (float*)d_out);
}

// round 5
// speedup vs baseline: 1.4358x; 1.1029x over previous
#include <cuda_runtime.h>
#include <cuda_fp16.h>
#include <math.h>

#define N_NODES 200000
#define HDIM 8
#define FIN 64
#define ROWB 32   // packed src row: 16B fp16 h + 4B fp32 as + 12B pad
#define PNODES 160  // nodes per proj block (200000 % 160 == 0)

// ---------------- constant-memory parameters --------------------------------
__constant__ float cW[3][FIN * HDIM];
__constant__ float cb[3][HDIM];
__constant__ float cAttSrc[4][HDIM];
__constant__ float cAttDst[4][HDIM];
__constant__ float cKW[HDIM * HDIM];
__constant__ float cKb[HDIM];
__constant__ float cQ[HDIM];
__constant__ float cLinW[2][HDIM];
__constant__ float cLinB[2];

// ---------------- scratch (static device globals; no allocation) -------------
__device__ char  g_pack[4][(size_t)N_NODES * ROWB]; // per edge type: packed src rows
__device__ float g_ad[4 * N_NODES];                 // per edge type: dst alpha
__device__ float g_den[4 * N_NODES];                // per-type softmax denominators
__device__ float g_out[4 * N_NODES * HDIM];         // 4 GAT outputs (UNNORMALIZED)
__device__ float g_score[4];

// ---------------- fused projection (all 3 node types, grid.y) ----------------
struct ProjCfg {
    const float* x[3];
    char* pack0[3]; int asrc0[3];   // packed output 0 (nullable) + att idx
    char* pack1[3]; int asrc1[3];   // packed output 1 (nullable)
    float* ad0[3];  int adst0[3];   // dst alpha output 0 (nullable)
    float* ad1[3];  int adst1[3];   // dst alpha output 1 (nullable)
};

__device__ __forceinline__ void write_pack(char* pack, size_t gn,
                                           const float* acc, const float* att)
{
    __half2 hh[4];
#pragma unroll
    for (int i = 0; i < 4; i++) hh[i] = __floats2half2_rn(acc[2 * i], acc[2 * i + 1]);
    char* row = pack + gn * ROWB;
    *reinterpret_cast<uint4*>(row) = *reinterpret_cast<uint4*>(hh);
    float as = 0.f;
#pragma unroll
    for (int j = 0; j < HDIM; j++) as += acc[j] * att[j];
    *reinterpret_cast<float*>(row + 16) = as;
}

__global__ __launch_bounds__(PNODES) void proj_kernel(ProjCfg C)
{
    int ty = blockIdx.y;
    const float* x = C.x[ty];
    __shared__ float4 sx[PNODES * 17];   // stride 17 float4 = 68 floats: conflict-free
    int tid = threadIdx.x;
    size_t base = (size_t)blockIdx.x * PNODES;

    const float4* xg = reinterpret_cast<const float4*>(x + base * FIN);
#pragma unroll 4
    for (int i = tid; i < PNODES * 16; i += PNODES) {
        int row = i >> 4, k4 = i & 15;
        sx[row * 17 + k4] = xg[i];
    }
    __syncthreads();

    const float* W = cW[ty];
    float acc[HDIM];
#pragma unroll
    for (int j = 0; j < HDIM; j++) acc[j] = cb[ty][j];
#pragma unroll
    for (int k4 = 0; k4 < 16; k4++) {
        float4 xv = sx[tid * 17 + k4];
#pragma unroll
        for (int j = 0; j < HDIM; j++) {
            acc[j] += xv.x * W[(4 * k4 + 0) * HDIM + j]
                    + xv.y * W[(4 * k4 + 1) * HDIM + j]
                    + xv.z * W[(4 * k4 + 2) * HDIM + j]
                    + xv.w * W[(4 * k4 + 3) * HDIM + j];
        }
    }

    size_t gn = base + tid;
    if (C.pack0[ty]) write_pack(C.pack0[ty], gn, acc, cAttSrc[C.asrc0[ty]]);
    if (C.pack1[ty]) write_pack(C.pack1[ty], gn, acc, cAttSrc[C.asrc1[ty]]);
    if (C.ad0[ty]) {
        const float* att = cAttDst[C.adst0[ty]];
        float v = 0.f;
#pragma unroll
        for (int j = 0; j < HDIM; j++) v += acc[j] * att[j];
        C.ad0[ty][gn] = v;
    }
    if (C.ad1[ty]) {
        const float* att = cAttDst[C.adst1[ty]];
        float v = 0.f;
#pragma unroll
        for (int j = 0; j < HDIM; j++) v += acc[j] * att[j];
        C.ad1[ty][gn] = v;
    }
}

// ---------------- fused edge pass (all 4 edge types, grid.y) -----------------
struct EdgeAll {
    const int*  ei[4];
    const char* pack[4];
    const float* ad[4];
    float* den[4];
    float* out[4];
    int E[4];
};

__device__ __forceinline__ void edge_one(int r, int c,
                                         const char* __restrict__ pack,
                                         const float* __restrict__ ad,
                                         float* __restrict__ den,
                                         float* __restrict__ out)
{
    const uint4* rowp = reinterpret_cast<const uint4*>(pack + (size_t)r * ROWB);
    uint4 hv = __ldg(rowp);                                      // 8 fp16 h
    float asv = __ldg(reinterpret_cast<const float*>(rowp) + 4); // same 32B sector
    float a = asv + __ldg(&ad[c]);
    a = (a > 0.f) ? a : 0.2f * a;
    float ex = __expf(a);

    const __half2* hp = reinterpret_cast<const __half2*>(&hv);
    float2 f0 = __half22float2(hp[0]);
    float2 f1 = __half22float2(hp[1]);
    float2 f2 = __half22float2(hp[2]);
    float2 f3 = __half22float2(hp[3]);

    float4* op = reinterpret_cast<float4*>(out + (size_t)c * HDIM);
    atomicAdd(op,     make_float4(f0.x * ex, f0.y * ex, f1.x * ex, f1.y * ex));
    atomicAdd(op + 1, make_float4(f2.x * ex, f2.y * ex, f3.x * ex, f3.y * ex));
    atomicAdd(&den[c], ex);
}

__global__ void edge_kernel(EdgeAll A)
{
    int t = blockIdx.y;
    int E = A.E[t];
    const int*  ei   = A.ei[t];
    const char* pack = A.pack[t];
    const float* ad  = A.ad[t];
    float* den = A.den[t];
    float* out = A.out[t];

    int i0 = (blockIdx.x * blockDim.x + threadIdx.x) * 4;
    if (i0 + 4 <= E) {
        int4 rr = __ldcs(reinterpret_cast<const int4*>(ei + i0));
        int4 cc = __ldcs(reinterpret_cast<const int4*>(ei + E + i0));
        edge_one(rr.x, cc.x, pack, ad, den, out);
        edge_one(rr.y, cc.y, pack, ad, den, out);
        edge_one(rr.z, cc.z, pack, ad, den, out);
        edge_one(rr.w, cc.w, pack, ad, den, out);
    } else {
        for (int i = i0; i < E; i++)
            edge_one(ei[i], ei[E + i], pack, ad, den, out);
    }
}

// ---------------- semantic score (all 4 metapaths, grid.y); inv inline -------
__global__ void score_kernel(const float* __restrict__ out_base,
                             const float* __restrict__ den_base,
                             float* __restrict__ score)
{
    int g = blockIdx.y;
    const float* o = out_base + (size_t)g * N_NODES * HDIM;
    const float* den = den_base + (size_t)g * N_NODES;
    int n = blockIdx.x * blockDim.x + threadIdx.x;
    float s = 0.f;
    if (n < N_NODES) {
        float inv = 1.f / (__ldg(&den[n]) + 1e-16f);
        const float4* op = reinterpret_cast<const float4*>(o + (size_t)n * HDIM);
        float4 o0 = __ldg(op), o1 = __ldg(op + 1);
        float orl[HDIM];
        orl[0] = fmaxf(o0.x * inv, 0.f); orl[1] = fmaxf(o0.y * inv, 0.f);
        orl[2] = fmaxf(o0.z * inv, 0.f); orl[3] = fmaxf(o0.w * inv, 0.f);
        orl[4] = fmaxf(o1.x * inv, 0.f); orl[5] = fmaxf(o1.y * inv, 0.f);
        orl[6] = fmaxf(o1.z * inv, 0.f); orl[7] = fmaxf(o1.w * inv, 0.f);
#pragma unroll
        for (int j = 0; j < HDIM; j++) {
            float acc = cKb[j];
#pragma unroll
            for (int k = 0; k < HDIM; k++) acc += orl[k] * cKW[k * HDIM + j];
            s += cQ[j] * tanhf(acc);
        }
    }
#pragma unroll
    for (int off = 16; off; off >>= 1) s += __shfl_xor_sync(0xffffffffu, s, off);
    __shared__ float ws[8];
    int lane = threadIdx.x & 31, wid = threadIdx.x >> 5;
    if (lane == 0) ws[wid] = s;
    __syncthreads();
    if (wid == 0) {
        s = (lane < 8) ? ws[lane] : 0.f;
#pragma unroll
        for (int off = 4; off; off >>= 1) s += __shfl_xor_sync(0xffffffffu, s, off);
        if (lane == 0) atomicAdd(&score[g], s);
    }
}

// ---------------- final heads (both groups, grid.y); attn softmax inline -----
__global__ void final_kernel(const float* __restrict__ out_base,
                             const float* __restrict__ den_base,
                             const float* __restrict__ score,
                             float* __restrict__ pred)
{
    int g = blockIdx.y;   // 0: ind (types 0,1), 1: org (types 2,3)
    int n = blockIdx.x * blockDim.x + threadIdx.x;
    if (n >= N_NODES) return;

    // semantic softmax over this group's 2 metapath scores (uniform per block)
    float s0 = __ldg(&score[2 * g])     * (1.f / (float)N_NODES);
    float s1 = __ldg(&score[2 * g + 1]) * (1.f / (float)N_NODES);
    float m  = fmaxf(s0, s1);
    float e0 = __expf(s0 - m), e1 = __expf(s1 - m);
    float winv = 1.f / (e0 + e1);
    float w0 = e0 * winv, w1 = e1 * winv;

    const float* o0 = out_base + (size_t)(2 * g)     * N_NODES * HDIM;
    const float* o1 = out_base + (size_t)(2 * g + 1) * N_NODES * HDIM;
    float i0 = 1.f / (__ldg(&den_base[(size_t)(2 * g)     * N_NODES + n]) + 1e-16f);
    float i1 = 1.f / (__ldg(&den_base[(size_t)(2 * g + 1) * N_NODES + n]) + 1e-16f);
    float s = cLinB[g];
#pragma unroll
    for (int j = 0; j < HDIM; j++) {
        float z = w0 * fmaxf(o0[(size_t)n * HDIM + j] * i0, 0.f)
                + w1 * fmaxf(o1[(size_t)n * HDIM + j] * i1, 0.f);
        s += z * cLinW[g][j];
    }
    pred[(size_t)g * N_NODES + n] = 1.f / (1.f + expf(-s));
}

// -----------------------------------------------------------------------------
static inline void cpy(void* dst, const void* src, size_t bytes) {
    cudaMemcpyAsync(dst, src, bytes, cudaMemcpyDeviceToDevice, 0);
}

extern "C" void kernel_launch(void* const* d_in, const int* in_sizes, int n_in,
                              void* d_out, int out_size)
{
    char  *p_pack; float *p_ad, *p_den, *p_out, *p_score;
    cudaGetSymbolAddress((void**)&p_pack, g_pack);
    cudaGetSymbolAddress((void**)&p_ad, g_ad);
    cudaGetSymbolAddress((void**)&p_den, g_den);
    cudaGetSymbolAddress((void**)&p_out, g_out);
    cudaGetSymbolAddress((void**)&p_score, g_score);

    char* pk[4];
    for (int t = 0; t < 4; t++) pk[t] = p_pack + (size_t)t * N_NODES * ROWB;

    // ---- copy parameters into __constant__ (graph-legal D2D memcpys) ----
    void *a_cW, *a_cb, *a_cAS, *a_cAD, *a_cKW, *a_cKb, *a_cQ, *a_cLW, *a_cLB;
    cudaGetSymbolAddress(&a_cW, cW);
    cudaGetSymbolAddress(&a_cb, cb);
    cudaGetSymbolAddress(&a_cAS, cAttSrc);
    cudaGetSymbolAddress(&a_cAD, cAttDst);
    cudaGetSymbolAddress(&a_cKW, cKW);
    cudaGetSymbolAddress(&a_cKb, cKb);
    cudaGetSymbolAddress(&a_cQ, cQ);
    cudaGetSymbolAddress(&a_cLW, cLinW);
    cudaGetSymbolAddress(&a_cLB, cLinB);

    const size_t WB = FIN * HDIM * sizeof(float), HB = HDIM * sizeof(float);
    cpy((char*)a_cW + 0 * WB, d_in[7],  WB);   // W_ind
    cpy((char*)a_cW + 1 * WB, d_in[9],  WB);   // W_org
    cpy((char*)a_cW + 2 * WB, d_in[11], WB);   // W_ext
    cpy((char*)a_cb + 0 * HB, d_in[8],  HB);
    cpy((char*)a_cb + 1 * HB, d_in[10], HB);
    cpy((char*)a_cb + 2 * HB, d_in[12], HB);
    // edge types: t0=org->ind, t1=ext->ind, t2=ind->org, t3=ext->org
    cpy((char*)a_cAS + 0 * HB, d_in[15], HB);  // att_src_org_ind
    cpy((char*)a_cAS + 1 * HB, d_in[17], HB);  // att_src_ext_ind
    cpy((char*)a_cAS + 2 * HB, d_in[13], HB);  // att_src_ind_org
    cpy((char*)a_cAS + 3 * HB, d_in[19], HB);  // att_src_ext_org
    cpy((char*)a_cAD + 0 * HB, d_in[16], HB);  // att_dst_org_ind
    cpy((char*)a_cAD + 1 * HB, d_in[18], HB);  // att_dst_ext_ind
    cpy((char*)a_cAD + 2 * HB, d_in[14], HB);  // att_dst_ind_org
    cpy((char*)a_cAD + 3 * HB, d_in[20], HB);  // att_dst_ext_org
    cpy(a_cKW, d_in[21], HDIM * HDIM * sizeof(float));
    cpy(a_cKb, d_in[22], HB);
    cpy(a_cQ,  d_in[23], HB);
    cpy((char*)a_cLW + 0 * HB, d_in[24], HB);
    cpy((char*)a_cLW + 1 * HB, d_in[26], HB);
    cpy((char*)a_cLB + 0, d_in[25], sizeof(float));
    cpy((char*)a_cLB + 4, d_in[27], sizeof(float));

    cudaMemsetAsync(p_out, 0, 4 * (size_t)N_NODES * HDIM * sizeof(float), 0);
    cudaMemsetAsync(p_den, 0, 4 * (size_t)N_NODES * sizeof(float), 0);
    cudaMemsetAsync(p_score, 0, 4 * sizeof(float), 0);

    // ---- projection ----
    ProjCfg PC;
    PC.x[0] = (const float*)d_in[0];  // ind
    PC.x[1] = (const float*)d_in[1];  // org
    PC.x[2] = (const float*)d_in[2];  // ext
    // ind: pack t2; dst alphas t0, t1
    PC.pack0[0] = pk[2]; PC.asrc0[0] = 2;  PC.pack1[0] = nullptr; PC.asrc1[0] = 0;
    PC.ad0[0] = p_ad + 0 * N_NODES; PC.adst0[0] = 0;
    PC.ad1[0] = p_ad + 1 * N_NODES; PC.adst1[0] = 1;
    // org: pack t0; dst alphas t2, t3
    PC.pack0[1] = pk[0]; PC.asrc0[1] = 0;  PC.pack1[1] = nullptr; PC.asrc1[1] = 0;
    PC.ad0[1] = p_ad + 2 * N_NODES; PC.adst0[1] = 2;
    PC.ad1[1] = p_ad + 3 * N_NODES; PC.adst1[1] = 3;
    // ext: pack t1, pack t3
    PC.pack0[2] = pk[1]; PC.asrc0[2] = 1;  PC.pack1[2] = pk[3]; PC.asrc1[2] = 3;
    PC.ad0[2] = nullptr; PC.adst0[2] = 0;
    PC.ad1[2] = nullptr; PC.adst1[2] = 0;

    dim3 pg(N_NODES / PNODES, 3);
    proj_kernel<<<pg, PNODES>>>(PC);

    // ---- edges ----
    EdgeAll EA;
    EA.ei[0] = (const int*)d_in[4]; EA.E[0] = in_sizes[4] / 2;  // org->ind
    EA.ei[1] = (const int*)d_in[5]; EA.E[1] = in_sizes[5] / 2;  // ext->ind
    EA.ei[2] = (const int*)d_in[3]; EA.E[2] = in_sizes[3] / 2;  // ind->org
    EA.ei[3] = (const int*)d_in[6]; EA.E[3] = in_sizes[6] / 2;  // ext->org
    int Emax = 0;
    for (int t = 0; t < 4; t++) {
        EA.pack[t] = pk[t];
        EA.ad[t]   = p_ad + (size_t)t * N_NODES;
        EA.den[t]  = p_den + (size_t)t * N_NODES;
        EA.out[t]  = p_out + (size_t)t * N_NODES * HDIM;
        if (EA.E[t] > Emax) Emax = EA.E[t];
    }
    dim3 eg((Emax / 4 + 255) / 256 + 1, 4);
    edge_kernel<<<eg, 256>>>(EA);

    // ---- semantic attention + heads ----
    const int NG = (N_NODES + 255) / 256;
    dim3 sg(NG, 4);
    score_kernel<<<sg, 256>>>(p_out, p_den, p_score);

    dim3 fg(NG, 2);
    final_kernel<<<fg, 256>>>(p_out, p_den, p_score, (float*)d_out);
}

// round 6
// speedup vs baseline: 1.5030x; 1.0468x over previous
#include <cuda_runtime.h>
#include <cuda_fp16.h>
#include <math.h>

#define N_NODES 200000
#define HDIM 8
#define FIN 64
#define ROWB 32     // packed src row: 16B fp16 h + 4B fp32 as + 12B pad
#define PNODES 160  // nodes per proj block (200000 % 160 == 0)

// ---------------- packed parameter block (constant + staging) ----------------
struct CParams {               // field order == gather segment order (all float)
    float W[3][FIN * HDIM];    // 3 x 512
    float b[3][HDIM];
    float attSrc[4][HDIM];     // t0..t3
    float attDst[4][HDIM];
    float kW[HDIM * HDIM];
    float kb[HDIM];
    float q[HDIM];
    float linW[2][HDIM];
    float linB[2];
};
__constant__ CParams cP;
__device__ CParams gStage;

// ---------------- scratch (static device globals; no allocation) -------------
__device__ char  g_pack[4][(size_t)N_NODES * ROWB]; // per edge type: packed src rows
__device__ float g_ad[4 * N_NODES];                 // per edge type: dst alpha
__device__ float g_acc[4 * N_NODES * HDIM + 4 * N_NODES]; // out (4*N*8) then den (4*N)
__device__ float g_score[4];

// ---------------- parameter gather (one block) --------------------------------
struct SrcPtrs { const float* p[21]; };

__global__ void gather_kernel(SrcPtrs S)
{
    const int len[21] = {512,512,512, 8,8,8, 8,8,8,8, 8,8,8,8, 64,8,8, 8,8, 1,1};
    float* dst = reinterpret_cast<float*>(&gStage);
    int off = 0;
    for (int s = 0; s < 21; s++) {
        const float* src = S.p[s];
        for (int i = threadIdx.x; i < len[s]; i += blockDim.x)
            dst[off + i] = src[i];
        off += len[s];
    }
    if (threadIdx.x < 4) g_score[threadIdx.x] = 0.f;
}

// ---------------- fused projection (all 3 node types, grid.y) ----------------
struct ProjCfg {
    const float* x[3];
    char* pack0[3]; int asrc0[3];
    char* pack1[3]; int asrc1[3];
    float* ad0[3];  int adst0[3];
    float* ad1[3];  int adst1[3];
};

__device__ __forceinline__ void write_pack(char* pack, size_t gn,
                                           const float* acc, const float* att)
{
    __half2 hh[4];
#pragma unroll
    for (int i = 0; i < 4; i++) hh[i] = __floats2half2_rn(acc[2 * i], acc[2 * i + 1]);
    char* row = pack + gn * ROWB;
    *reinterpret_cast<uint4*>(row) = *reinterpret_cast<uint4*>(hh);
    float as = 0.f;
#pragma unroll
    for (int j = 0; j < HDIM; j++) as += acc[j] * att[j];
    *reinterpret_cast<float*>(row + 16) = as;
}

__global__ __launch_bounds__(PNODES) void proj_kernel(ProjCfg C)
{
    int ty = blockIdx.y;
    const float* x = C.x[ty];
    __shared__ float4 sx[PNODES * 17];   // stride-17 float4: conflict-free
    int tid = threadIdx.x;
    size_t base = (size_t)blockIdx.x * PNODES;

    const float4* xg = reinterpret_cast<const float4*>(x + base * FIN);
#pragma unroll 4
    for (int i = tid; i < PNODES * 16; i += PNODES) {
        int row = i >> 4, k4 = i & 15;
        sx[row * 17 + k4] = xg[i];
    }
    __syncthreads();

    const float* W = cP.W[ty];
    float acc[HDIM];
#pragma unroll
    for (int j = 0; j < HDIM; j++) acc[j] = cP.b[ty][j];
#pragma unroll
    for (int k4 = 0; k4 < 16; k4++) {
        float4 xv = sx[tid * 17 + k4];
#pragma unroll
        for (int j = 0; j < HDIM; j++) {
            acc[j] += xv.x * W[(4 * k4 + 0) * HDIM + j]
                    + xv.y * W[(4 * k4 + 1) * HDIM + j]
                    + xv.z * W[(4 * k4 + 2) * HDIM + j]
                    + xv.w * W[(4 * k4 + 3) * HDIM + j];
        }
    }

    size_t gn = base + tid;
    if (C.pack0[ty]) write_pack(C.pack0[ty], gn, acc, cP.attSrc[C.asrc0[ty]]);
    if (C.pack1[ty]) write_pack(C.pack1[ty], gn, acc, cP.attSrc[C.asrc1[ty]]);
    if (C.ad0[ty]) {
        const float* att = cP.attDst[C.adst0[ty]];
        float v = 0.f;
#pragma unroll
        for (int j = 0; j < HDIM; j++) v += acc[j] * att[j];
        C.ad0[ty][gn] = v;
    }
    if (C.ad1[ty]) {
        const float* att = cP.attDst[C.adst1[ty]];
        float v = 0.f;
#pragma unroll
        for (int j = 0; j < HDIM; j++) v += acc[j] * att[j];
        C.ad1[ty][gn] = v;
    }
}

// ---------------- fused edge pass (all 4 edge types, grid.y) -----------------
struct EdgeAll {
    const int*  ei[4];
    const char* pack[4];
    const float* ad[4];
    float* den[4];
    float* out[4];
    int E[4];
};

__device__ __forceinline__ void edge_one(int r, int c,
                                         const char* __restrict__ pack,
                                         const float* __restrict__ ad,
                                         float* __restrict__ den,
                                         float* __restrict__ out)
{
    const uint4* rowp = reinterpret_cast<const uint4*>(pack + (size_t)r * ROWB);
    uint4 hv = __ldg(rowp);                                      // 8 fp16 h
    float asv = __ldg(reinterpret_cast<const float*>(rowp) + 4); // same 32B sector
    float a = asv + __ldg(&ad[c]);
    a = (a > 0.f) ? a : 0.2f * a;
    float ex = __expf(a);

    const __half2* hp = reinterpret_cast<const __half2*>(&hv);
    float2 f0 = __half22float2(hp[0]);
    float2 f1 = __half22float2(hp[1]);
    float2 f2 = __half22float2(hp[2]);
    float2 f3 = __half22float2(hp[3]);

    float4* op = reinterpret_cast<float4*>(out + (size_t)c * HDIM);
    atomicAdd(op,     make_float4(f0.x * ex, f0.y * ex, f1.x * ex, f1.y * ex));
    atomicAdd(op + 1, make_float4(f2.x * ex, f2.y * ex, f3.x * ex, f3.y * ex));
    atomicAdd(&den[c], ex);
}

__global__ void edge_kernel(EdgeAll A)
{
    int t = blockIdx.y;
    int E = A.E[t];
    const int*  ei   = A.ei[t];
    const char* pack = A.pack[t];
    const float* ad  = A.ad[t];
    float* den = A.den[t];
    float* out = A.out[t];

    int i0 = (blockIdx.x * blockDim.x + threadIdx.x) * 4;
    if (i0 + 4 <= E) {
        int4 rr = __ldcs(reinterpret_cast<const int4*>(ei + i0));
        int4 cc = __ldcs(reinterpret_cast<const int4*>(ei + E + i0));
        edge_one(rr.x, cc.x, pack, ad, den, out);
        edge_one(rr.y, cc.y, pack, ad, den, out);
        edge_one(rr.z, cc.z, pack, ad, den, out);
        edge_one(rr.w, cc.w, pack, ad, den, out);
    } else {
        for (int i = i0; i < E; i++)
            edge_one(ei[i], ei[E + i], pack, ad, den, out);
    }
}

// ---------------- semantic score (all 4 metapaths, grid.y); inv inline -------
__global__ void score_kernel(const float* __restrict__ out_base,
                             const float* __restrict__ den_base,
                             float* __restrict__ score)
{
    int g = blockIdx.y;
    const float* o = out_base + (size_t)g * N_NODES * HDIM;
    const float* den = den_base + (size_t)g * N_NODES;
    int n = blockIdx.x * blockDim.x + threadIdx.x;
    float s = 0.f;
    if (n < N_NODES) {
        float inv = 1.f / (__ldg(&den[n]) + 1e-16f);
        const float4* op = reinterpret_cast<const float4*>(o + (size_t)n * HDIM);
        float4 o0 = __ldg(op), o1 = __ldg(op + 1);
        float orl[HDIM];
        orl[0] = fmaxf(o0.x * inv, 0.f); orl[1] = fmaxf(o0.y * inv, 0.f);
        orl[2] = fmaxf(o0.z * inv, 0.f); orl[3] = fmaxf(o0.w * inv, 0.f);
        orl[4] = fmaxf(o1.x * inv, 0.f); orl[5] = fmaxf(o1.y * inv, 0.f);
        orl[6] = fmaxf(o1.z * inv, 0.f); orl[7] = fmaxf(o1.w * inv, 0.f);
#pragma unroll
        for (int j = 0; j < HDIM; j++) {
            float acc = cP.kb[j];
#pragma unroll
            for (int k = 0; k < HDIM; k++) acc += orl[k] * cP.kW[k * HDIM + j];
            s += cP.q[j] * tanhf(acc);
        }
    }
#pragma unroll
    for (int off = 16; off; off >>= 1) s += __shfl_xor_sync(0xffffffffu, s, off);
    __shared__ float ws[8];
    int lane = threadIdx.x & 31, wid = threadIdx.x >> 5;
    if (lane == 0) ws[wid] = s;
    __syncthreads();
    if (wid == 0) {
        s = (lane < 8) ? ws[lane] : 0.f;
#pragma unroll
        for (int off = 4; off; off >>= 1) s += __shfl_xor_sync(0xffffffffu, s, off);
        if (lane == 0) atomicAdd(&score[g], s);
    }
}

// ---------------- final heads (both groups, grid.y); attn softmax inline -----
__global__ void final_kernel(const float* __restrict__ out_base,
                             const float* __restrict__ den_base,
                             const float* __restrict__ score,
                             float* __restrict__ pred)
{
    int g = blockIdx.y;   // 0: ind (types 0,1), 1: org (types 2,3)
    int n = blockIdx.x * blockDim.x + threadIdx.x;
    if (n >= N_NODES) return;

    float s0 = __ldg(&score[2 * g])     * (1.f / (float)N_NODES);
    float s1 = __ldg(&score[2 * g + 1]) * (1.f / (float)N_NODES);
    float m  = fmaxf(s0, s1);
    float e0 = __expf(s0 - m), e1 = __expf(s1 - m);
    float winv = 1.f / (e0 + e1);
    float w0 = e0 * winv, w1 = e1 * winv;

    const float* o0 = out_base + (size_t)(2 * g)     * N_NODES * HDIM;
    const float* o1 = out_base + (size_t)(2 * g + 1) * N_NODES * HDIM;
    float i0 = 1.f / (__ldg(&den_base[(size_t)(2 * g)     * N_NODES + n]) + 1e-16f);
    float i1 = 1.f / (__ldg(&den_base[(size_t)(2 * g + 1) * N_NODES + n]) + 1e-16f);
    float s = cP.linB[g];
#pragma unroll
    for (int j = 0; j < HDIM; j++) {
        float z = w0 * fmaxf(o0[(size_t)n * HDIM + j] * i0, 0.f)
                + w1 * fmaxf(o1[(size_t)n * HDIM + j] * i1, 0.f);
        s += z * cP.linW[g][j];
    }
    pred[(size_t)g * N_NODES + n] = 1.f / (1.f + expf(-s));
}

// -----------------------------------------------------------------------------
extern "C" void kernel_launch(void* const* d_in, const int* in_sizes, int n_in,
                              void* d_out, int out_size)
{
    char *p_pack; float *p_ad, *p_acc, *p_score;
    cudaGetSymbolAddress((void**)&p_pack, g_pack);
    cudaGetSymbolAddress((void**)&p_ad, g_ad);
    cudaGetSymbolAddress((void**)&p_acc, g_acc);
    cudaGetSymbolAddress((void**)&p_score, g_score);
    void *a_cP, *a_stage;
    cudaGetSymbolAddress(&a_cP, cP);
    cudaGetSymbolAddress(&a_stage, gStage);

    float* p_out = p_acc;                                     // 4*N*8
    float* p_den = p_acc + 4 * (size_t)N_NODES * HDIM;        // 4*N

    char* pk[4];
    for (int t = 0; t < 4; t++) pk[t] = p_pack + (size_t)t * N_NODES * ROWB;

    // ---- params: gather into staging, then ONE copy into constant bank ----
    SrcPtrs SP;
    SP.p[0]  = (const float*)d_in[7];   // W_ind
    SP.p[1]  = (const float*)d_in[9];   // W_org
    SP.p[2]  = (const float*)d_in[11];  // W_ext
    SP.p[3]  = (const float*)d_in[8];   // b_ind
    SP.p[4]  = (const float*)d_in[10];  // b_org
    SP.p[5]  = (const float*)d_in[12];  // b_ext
    // attSrc, edge types t0=org->ind, t1=ext->ind, t2=ind->org, t3=ext->org
    SP.p[6]  = (const float*)d_in[15];
    SP.p[7]  = (const float*)d_in[17];
    SP.p[8]  = (const float*)d_in[13];
    SP.p[9]  = (const float*)d_in[19];
    // attDst
    SP.p[10] = (const float*)d_in[16];
    SP.p[11] = (const float*)d_in[18];
    SP.p[12] = (const float*)d_in[14];
    SP.p[13] = (const float*)d_in[20];
    SP.p[14] = (const float*)d_in[21];  // kW
    SP.p[15] = (const float*)d_in[22];  // kb
    SP.p[16] = (const float*)d_in[23];  // q
    SP.p[17] = (const float*)d_in[24];  // lin_ind_W
    SP.p[18] = (const float*)d_in[26];  // lin_org_W
    SP.p[19] = (const float*)d_in[25];  // lin_ind_b
    SP.p[20] = (const float*)d_in[27];  // lin_org_b
    gather_kernel<<<1, 256>>>(SP);
    cudaMemcpyAsync(a_cP, a_stage, sizeof(CParams), cudaMemcpyDeviceToDevice, 0);

    cudaMemsetAsync(p_acc, 0,
                    (4 * (size_t)N_NODES * HDIM + 4 * (size_t)N_NODES) * sizeof(float), 0);

    // ---- projection ----
    ProjCfg PC;
    PC.x[0] = (const float*)d_in[0];
    PC.x[1] = (const float*)d_in[1];
    PC.x[2] = (const float*)d_in[2];
    PC.pack0[0] = pk[2]; PC.asrc0[0] = 2;  PC.pack1[0] = nullptr; PC.asrc1[0] = 0;
    PC.ad0[0] = p_ad + 0 * N_NODES; PC.adst0[0] = 0;
    PC.ad1[0] = p_ad + 1 * N_NODES; PC.adst1[0] = 1;
    PC.pack0[1] = pk[0]; PC.asrc0[1] = 0;  PC.pack1[1] = nullptr; PC.asrc1[1] = 0;
    PC.ad0[1] = p_ad + 2 * N_NODES; PC.adst0[1] = 2;
    PC.ad1[1] = p_ad + 3 * N_NODES; PC.adst1[1] = 3;
    PC.pack0[2] = pk[1]; PC.asrc0[2] = 1;  PC.pack1[2] = pk[3]; PC.asrc1[2] = 3;
    PC.ad0[2] = nullptr; PC.adst0[2] = 0;
    PC.ad1[2] = nullptr; PC.adst1[2] = 0;

    dim3 pg(N_NODES / PNODES, 3);
    proj_kernel<<<pg, PNODES>>>(PC);

    // ---- edges ----
    EdgeAll EA;
    EA.ei[0] = (const int*)d_in[4]; EA.E[0] = in_sizes[4] / 2;  // org->ind
    EA.ei[1] = (const int*)d_in[5]; EA.E[1] = in_sizes[5] / 2;  // ext->ind
    EA.ei[2] = (const int*)d_in[3]; EA.E[2] = in_sizes[3] / 2;  // ind->org
    EA.ei[3] = (const int*)d_in[6]; EA.E[3] = in_sizes[6] / 2;  // ext->org
    int Emax = 0;
    for (int t = 0; t < 4; t++) {
        EA.pack[t] = pk[t];
        EA.ad[t]   = p_ad + (size_t)t * N_NODES;
        EA.den[t]  = p_den + (size_t)t * N_NODES;
        EA.out[t]  = p_out + (size_t)t * N_NODES * HDIM;
        if (EA.E[t] > Emax) Emax = EA.E[t];
    }
    dim3 eg((Emax / 4 + 255) / 256 + 1, 4);
    edge_kernel<<<eg, 256>>>(EA);

    // ---- semantic attention + heads ----
    const int NG = (N_NODES + 255) / 256;
    dim3 sg(NG, 4);
    score_kernel<<<sg, 256>>>(p_out, p_den, p_score);

    dim3 fg(NG, 2);
    final_kernel<<<fg, 256>>>(p_out, p_den, p_score, (float*)d_out);
}

// round 7
// speedup vs baseline: 1.8187x; 1.2101x over previous
#include <cuda_runtime.h>
#include <cuda_fp16.h>
#include <math.h>

#define N_NODES 200000
#define HDIM 8
#define FIN 64
#define ROWB 32     // packed src row: 16B fp16 h + 4B fp32 as + 12B pad
#define PNODES 160  // nodes per proj block (200000 % 160 == 0)

// ---------------- packed parameter block (constant + staging) ----------------
struct CParams {               // field order == gather segment order (all float)
    float W[3][FIN * HDIM];    // 3 x 512
    float b[3][HDIM];
    float attSrc[4][HDIM];     // t0..t3
    float attDst[4][HDIM];
    float kW[HDIM * HDIM];
    float kb[HDIM];
    float q[HDIM];
    float linW[2][HDIM];
    float linB[2];
};
__constant__ CParams cP;
__device__ CParams gStage;

// ---------------- scratch (static device globals; no allocation) -------------
// out: 4*N*8 fp16 (12.8MB) followed by den: 4*N fp32 (3.2MB), one memset
#define OUT_BYTES (4 * (size_t)N_NODES * HDIM * 2)
#define DEN_BYTES (4 * (size_t)N_NODES * 4)
__device__ __align__(16) char g_accbuf[OUT_BYTES + DEN_BYTES];
__device__ char  g_pack[4][(size_t)N_NODES * ROWB]; // per edge type: packed src rows
__device__ float g_ad[4 * N_NODES];                 // per edge type: dst alpha
__device__ float g_score[4];

// ---------------- parameter gather (one block) --------------------------------
struct SrcPtrs { const float* p[21]; };

__global__ void gather_kernel(SrcPtrs S)
{
    const int len[21] = {512,512,512, 8,8,8, 8,8,8,8, 8,8,8,8, 64,8,8, 8,8, 1,1};
    float* dst = reinterpret_cast<float*>(&gStage);
    int off = 0;
    for (int s = 0; s < 21; s++) {
        const float* src = S.p[s];
        for (int i = threadIdx.x; i < len[s]; i += blockDim.x)
            dst[off + i] = src[i];
        off += len[s];
    }
    if (threadIdx.x < 4) g_score[threadIdx.x] = 0.f;
}

// ---------------- fused projection (all 3 node types, grid.y) ----------------
struct ProjCfg {
    const float* x[3];
    char* pack0[3]; int asrc0[3];
    char* pack1[3]; int asrc1[3];
    float* ad0[3];  int adst0[3];
    float* ad1[3];  int adst1[3];
};

__device__ __forceinline__ void write_pack(char* pack, size_t gn,
                                           const float* acc, const float* att)
{
    __half2 hh[4];
#pragma unroll
    for (int i = 0; i < 4; i++) hh[i] = __floats2half2_rn(acc[2 * i], acc[2 * i + 1]);
    char* row = pack + gn * ROWB;
    *reinterpret_cast<uint4*>(row) = *reinterpret_cast<uint4*>(hh);
    float as = 0.f;
#pragma unroll
    for (int j = 0; j < HDIM; j++) as += acc[j] * att[j];
    *reinterpret_cast<float*>(row + 16) = as;
}

__global__ __launch_bounds__(PNODES) void proj_kernel(ProjCfg C)
{
    int ty = blockIdx.y;
    const float* x = C.x[ty];
    __shared__ float4 sx[PNODES * 17];   // stride-17 float4: conflict-free
    int tid = threadIdx.x;
    size_t base = (size_t)blockIdx.x * PNODES;

    const float4* xg = reinterpret_cast<const float4*>(x + base * FIN);
#pragma unroll 4
    for (int i = tid; i < PNODES * 16; i += PNODES) {
        int row = i >> 4, k4 = i & 15;
        sx[row * 17 + k4] = xg[i];
    }
    __syncthreads();

    const float* W = cP.W[ty];
    float acc[HDIM];
#pragma unroll
    for (int j = 0; j < HDIM; j++) acc[j] = cP.b[ty][j];
#pragma unroll
    for (int k4 = 0; k4 < 16; k4++) {
        float4 xv = sx[tid * 17 + k4];
#pragma unroll
        for (int j = 0; j < HDIM; j++) {
            acc[j] += xv.x * W[(4 * k4 + 0) * HDIM + j]
                    + xv.y * W[(4 * k4 + 1) * HDIM + j]
                    + xv.z * W[(4 * k4 + 2) * HDIM + j]
                    + xv.w * W[(4 * k4 + 3) * HDIM + j];
        }
    }

    size_t gn = base + tid;
    if (C.pack0[ty]) write_pack(C.pack0[ty], gn, acc, cP.attSrc[C.asrc0[ty]]);
    if (C.pack1[ty]) write_pack(C.pack1[ty], gn, acc, cP.attSrc[C.asrc1[ty]]);
    if (C.ad0[ty]) {
        const float* att = cP.attDst[C.adst0[ty]];
        float v = 0.f;
#pragma unroll
        for (int j = 0; j < HDIM; j++) v += acc[j] * att[j];
        C.ad0[ty][gn] = v;
    }
    if (C.ad1[ty]) {
        const float* att = cP.attDst[C.adst1[ty]];
        float v = 0.f;
#pragma unroll
        for (int j = 0; j < HDIM; j++) v += acc[j] * att[j];
        C.ad1[ty][gn] = v;
    }
}

// ---------------- fused edge pass (all 4 edge types, grid.y) -----------------
struct EdgeAll {
    const int*  ei[4];
    const char* pack[4];
    const float* ad[4];
    float* den[4];
    __half* out[4];
    int E[4];
};

__device__ __forceinline__ void edge_one(int r, int c,
                                         const char* __restrict__ pack,
                                         const float* __restrict__ ad,
                                         float* __restrict__ den,
                                         __half* __restrict__ out)
{
    const uint4* rowp = reinterpret_cast<const uint4*>(pack + (size_t)r * ROWB);
    uint4 hv = __ldg(rowp);                                      // 8 fp16 h
    float asv = __ldg(reinterpret_cast<const float*>(rowp) + 4); // same 32B sector
    float a = asv + __ldg(&ad[c]);
    a = (a > 0.f) ? a : 0.2f * a;
    float ex = __expf(a);

    const __half2* hp = reinterpret_cast<const __half2*>(&hv);
    float2 f0 = __half22float2(hp[0]);
    float2 f1 = __half22float2(hp[1]);
    float2 f2 = __half22float2(hp[2]);
    float2 f3 = __half22float2(hp[3]);

    // products in fp32, single rounding to fp16, one 16B vector red
    __half2 m0 = __floats2half2_rn(f0.x * ex, f0.y * ex);
    __half2 m1 = __floats2half2_rn(f1.x * ex, f1.y * ex);
    __half2 m2 = __floats2half2_rn(f2.x * ex, f2.y * ex);
    __half2 m3 = __floats2half2_rn(f3.x * ex, f3.y * ex);

    __half* op = out + (size_t)c * HDIM;
    asm volatile("red.global.add.noftz.v4.f16x2 [%0], {%1, %2, %3, %4};"
                 :: "l"(op),
                    "r"(*reinterpret_cast<unsigned*>(&m0)),
                    "r"(*reinterpret_cast<unsigned*>(&m1)),
                    "r"(*reinterpret_cast<unsigned*>(&m2)),
                    "r"(*reinterpret_cast<unsigned*>(&m3))
                 : "memory");
    atomicAdd(&den[c], ex);
}

__global__ void edge_kernel(EdgeAll A)
{
    int t = blockIdx.y;
    int E = A.E[t];
    const int*  ei   = A.ei[t];
    const char* pack = A.pack[t];
    const float* ad  = A.ad[t];
    float* den = A.den[t];
    __half* out = A.out[t];

    int i0 = (blockIdx.x * blockDim.x + threadIdx.x) * 4;
    if (i0 + 4 <= E) {
        int4 rr = __ldcs(reinterpret_cast<const int4*>(ei + i0));
        int4 cc = __ldcs(reinterpret_cast<const int4*>(ei + E + i0));
        edge_one(rr.x, cc.x, pack, ad, den, out);
        edge_one(rr.y, cc.y, pack, ad, den, out);
        edge_one(rr.z, cc.z, pack, ad, den, out);
        edge_one(rr.w, cc.w, pack, ad, den, out);
    } else {
        for (int i = i0; i < E; i++)
            edge_one(ei[i], ei[E + i], pack, ad, den, out);
    }
}

// ---------------- semantic score (all 4 metapaths, grid.y); inv inline -------
__global__ void score_kernel(const __half* __restrict__ out_base,
                             const float* __restrict__ den_base,
                             float* __restrict__ score)
{
    int g = blockIdx.y;
    const __half* o = out_base + (size_t)g * N_NODES * HDIM;
    const float* den = den_base + (size_t)g * N_NODES;
    int n = blockIdx.x * blockDim.x + threadIdx.x;
    float s = 0.f;
    if (n < N_NODES) {
        float inv = 1.f / (__ldg(&den[n]) + 1e-16f);
        uint4 hv = __ldg(reinterpret_cast<const uint4*>(o + (size_t)n * HDIM));
        const __half2* hp = reinterpret_cast<const __half2*>(&hv);
        float2 f0 = __half22float2(hp[0]);
        float2 f1 = __half22float2(hp[1]);
        float2 f2 = __half22float2(hp[2]);
        float2 f3 = __half22float2(hp[3]);
        float orl[HDIM];
        orl[0] = fmaxf(f0.x * inv, 0.f); orl[1] = fmaxf(f0.y * inv, 0.f);
        orl[2] = fmaxf(f1.x * inv, 0.f); orl[3] = fmaxf(f1.y * inv, 0.f);
        orl[4] = fmaxf(f2.x * inv, 0.f); orl[5] = fmaxf(f2.y * inv, 0.f);
        orl[6] = fmaxf(f3.x * inv, 0.f); orl[7] = fmaxf(f3.y * inv, 0.f);
#pragma unroll
        for (int j = 0; j < HDIM; j++) {
            float acc = cP.kb[j];
#pragma unroll
            for (int k = 0; k < HDIM; k++) acc += orl[k] * cP.kW[k * HDIM + j];
            s += cP.q[j] * tanhf(acc);
        }
    }
#pragma unroll
    for (int off = 16; off; off >>= 1) s += __shfl_xor_sync(0xffffffffu, s, off);
    __shared__ float ws[8];
    int lane = threadIdx.x & 31, wid = threadIdx.x >> 5;
    if (lane == 0) ws[wid] = s;
    __syncthreads();
    if (wid == 0) {
        s = (lane < 8) ? ws[lane] : 0.f;
#pragma unroll
        for (int off = 4; off; off >>= 1) s += __shfl_xor_sync(0xffffffffu, s, off);
        if (lane == 0) atomicAdd(&score[g], s);
    }
}

// ---------------- final heads (both groups, grid.y); attn softmax inline -----
__global__ void final_kernel(const __half* __restrict__ out_base,
                             const float* __restrict__ den_base,
                             const float* __restrict__ score,
                             float* __restrict__ pred)
{
    int g = blockIdx.y;   // 0: ind (types 0,1), 1: org (types 2,3)
    int n = blockIdx.x * blockDim.x + threadIdx.x;
    if (n >= N_NODES) return;

    float s0 = __ldg(&score[2 * g])     * (1.f / (float)N_NODES);
    float s1 = __ldg(&score[2 * g + 1]) * (1.f / (float)N_NODES);
    float m  = fmaxf(s0, s1);
    float e0 = __expf(s0 - m), e1 = __expf(s1 - m);
    float winv = 1.f / (e0 + e1);
    float w0 = e0 * winv, w1 = e1 * winv;

    const __half* o0 = out_base + (size_t)(2 * g)     * N_NODES * HDIM;
    const __half* o1 = out_base + (size_t)(2 * g + 1) * N_NODES * HDIM;
    float i0 = 1.f / (__ldg(&den_base[(size_t)(2 * g)     * N_NODES + n]) + 1e-16f);
    float i1 = 1.f / (__ldg(&den_base[(size_t)(2 * g + 1) * N_NODES + n]) + 1e-16f);

    uint4 hv0 = __ldg(reinterpret_cast<const uint4*>(o0 + (size_t)n * HDIM));
    uint4 hv1 = __ldg(reinterpret_cast<const uint4*>(o1 + (size_t)n * HDIM));
    const __half2* hp0 = reinterpret_cast<const __half2*>(&hv0);
    const __half2* hp1 = reinterpret_cast<const __half2*>(&hv1);

    float s = cP.linB[g];
#pragma unroll
    for (int p = 0; p < 4; p++) {
        float2 a = __half22float2(hp0[p]);
        float2 b = __half22float2(hp1[p]);
        float z0 = w0 * fmaxf(a.x * i0, 0.f) + w1 * fmaxf(b.x * i1, 0.f);
        float z1 = w0 * fmaxf(a.y * i0, 0.f) + w1 * fmaxf(b.y * i1, 0.f);
        s += z0 * cP.linW[g][2 * p] + z1 * cP.linW[g][2 * p + 1];
    }
    pred[(size_t)g * N_NODES + n] = 1.f / (1.f + expf(-s));
}

// -----------------------------------------------------------------------------
extern "C" void kernel_launch(void* const* d_in, const int* in_sizes, int n_in,
                              void* d_out, int out_size)
{
    char *p_pack, *p_accbuf; float *p_ad, *p_score;
    cudaGetSymbolAddress((void**)&p_pack, g_pack);
    cudaGetSymbolAddress((void**)&p_accbuf, g_accbuf);
    cudaGetSymbolAddress((void**)&p_ad, g_ad);
    cudaGetSymbolAddress((void**)&p_score, g_score);
    void *a_cP, *a_stage;
    cudaGetSymbolAddress(&a_cP, cP);
    cudaGetSymbolAddress(&a_stage, gStage);

    __half* p_out = reinterpret_cast<__half*>(p_accbuf);
    float*  p_den = reinterpret_cast<float*>(p_accbuf + OUT_BYTES);

    char* pk[4];
    for (int t = 0; t < 4; t++) pk[t] = p_pack + (size_t)t * N_NODES * ROWB;

    // ---- params: gather into staging, then ONE copy into constant bank ----
    SrcPtrs SP;
    SP.p[0]  = (const float*)d_in[7];   // W_ind
    SP.p[1]  = (const float*)d_in[9];   // W_org
    SP.p[2]  = (const float*)d_in[11];  // W_ext
    SP.p[3]  = (const float*)d_in[8];   // b_ind
    SP.p[4]  = (const float*)d_in[10];  // b_org
    SP.p[5]  = (const float*)d_in[12];  // b_ext
    // attSrc, edge types t0=org->ind, t1=ext->ind, t2=ind->org, t3=ext->org
    SP.p[6]  = (const float*)d_in[15];
    SP.p[7]  = (const float*)d_in[17];
    SP.p[8]  = (const float*)d_in[13];
    SP.p[9]  = (const float*)d_in[19];
    // attDst
    SP.p[10] = (const float*)d_in[16];
    SP.p[11] = (const float*)d_in[18];
    SP.p[12] = (const float*)d_in[14];
    SP.p[13] = (const float*)d_in[20];
    SP.p[14] = (const float*)d_in[21];  // kW
    SP.p[15] = (const float*)d_in[22];  // kb
    SP.p[16] = (const float*)d_in[23];  // q
    SP.p[17] = (const float*)d_in[24];  // lin_ind_W
    SP.p[18] = (const float*)d_in[26];  // lin_org_W
    SP.p[19] = (const float*)d_in[25];  // lin_ind_b
    SP.p[20] = (const float*)d_in[27];  // lin_org_b
    gather_kernel<<<1, 256>>>(SP);
    cudaMemcpyAsync(a_cP, a_stage, sizeof(CParams), cudaMemcpyDeviceToDevice, 0);

    cudaMemsetAsync(p_accbuf, 0, OUT_BYTES + DEN_BYTES, 0);

    // ---- projection ----
    ProjCfg PC;
    PC.x[0] = (const float*)d_in[0];
    PC.x[1] = (const float*)d_in[1];
    PC.x[2] = (const float*)d_in[2];
    PC.pack0[0] = pk[2]; PC.asrc0[0] = 2;  PC.pack1[0] = nullptr; PC.asrc1[0] = 0;
    PC.ad0[0] = p_ad + 0 * N_NODES; PC.adst0[0] = 0;
    PC.ad1[0] = p_ad + 1 * N_NODES; PC.adst1[0] = 1;
    PC.pack0[1] = pk[0]; PC.asrc0[1] = 0;  PC.pack1[1] = nullptr; PC.asrc1[1] = 0;
    PC.ad0[1] = p_ad + 2 * N_NODES; PC.adst0[1] = 2;
    PC.ad1[1] = p_ad + 3 * N_NODES; PC.adst1[1] = 3;
    PC.pack0[2] = pk[1]; PC.asrc0[2] = 1;  PC.pack1[2] = pk[3]; PC.asrc1[2] = 3;
    PC.ad0[2] = nullptr; PC.adst0[2] = 0;
    PC.ad1[2] = nullptr; PC.adst1[2] = 0;

    dim3 pg(N_NODES / PNODES, 3);
    proj_kernel<<<pg, PNODES>>>(PC);

    // ---- edges ----
    EdgeAll EA;
    EA.ei[0] = (const int*)d_in[4]; EA.E[0] = in_sizes[4] / 2;  // org->ind
    EA.ei[1] = (const int*)d_in[5]; EA.E[1] = in_sizes[5] / 2;  // ext->ind
    EA.ei[2] = (const int*)d_in[3]; EA.E[2] = in_sizes[3] / 2;  // ind->org
    EA.ei[3] = (const int*)d_in[6]; EA.E[3] = in_sizes[6] / 2;  // ext->org
    int Emax = 0;
    for (int t = 0; t < 4; t++) {
        EA.pack[t] = pk[t];
        EA.ad[t]   = p_ad + (size_t)t * N_NODES;
        EA.den[t]  = p_den + (size_t)t * N_NODES;
        EA.out[t]  = p_out + (size_t)t * N_NODES * HDIM;
        if (EA.E[t] > Emax) Emax = EA.E[t];
    }
    dim3 eg((Emax / 4 + 255) / 256 + 1, 4);
    edge_kernel<<<eg, 256>>>(EA);

    // ---- semantic attention + heads ----
    const int NG = (N_NODES + 255) / 256;
    dim3 sg(NG, 4);
    score_kernel<<<sg, 256>>>(p_out, p_den, p_score);

    dim3 fg(NG, 2);
    final_kernel<<<fg, 256>>>(p_out, p_den, p_score, (float*)d_out);
}